// round 11
// baseline (speedup 1.0000x reference)
#include <cuda_runtime.h>
#include <cuda_bf16.h>
#include <cuda_fp16.h>
#include <cstdint>

// ---------------------------------------------------------------------------
// Problem constants: B=1, L=512, C_S=384, H=12, D=32
// ---------------------------------------------------------------------------
#define LSEQ   512
#define CS     384
#define NH     12
#define HD     32
#define ZROWS  (LSEQ*LSEQ)
#define PLANE  (LSEQ*LSEQ)

// Scratch (device globals: no allocation inside kernel_launch)
__device__ float g_q[LSEQ*CS];
__device__ float g_kv[LSEQ*2*CS];
__device__ float g_biasg[24ull*PLANE];   // n<12: bias head n ; n>=12: gate logit head n-12
__device__ float g_o[LSEQ*CS];
// B in mma-fragment order: [ks(24)][nc(3)][lane(32)] -> uint2 {b0(half2), b1(half2)}
__device__ uint2 g_bfrag[24*3*32];

// ---------------------------------------------------------------------------
// W prep: fused weights -> fp16 fragment layout.
// ---------------------------------------------------------------------------
__global__ void bprep_kernel(const float* __restrict__ Wb, const float* __restrict__ Wg) {
    int idx = blockIdx.x*256 + threadIdx.x;
    if (idx >= 24*3*32) return;
    int lane = idx & 31, step = idx >> 5;
    int ks = step / 3, nc = step % 3;
    int gid = lane >> 2, qid = lane & 3;
    int n = nc*8 + gid;
    int k0 = ks*16 + qid*2;

    auto w = [&](int k) -> float {
        return (n < NH) ? Wb[k*NH + n] : Wg[k*NH + (n - NH)];
    };
    __half2 b0 = __float22half2_rn(make_float2(w(k0),   w(k0+1)));
    __half2 b1 = __float22half2_rn(make_float2(w(k0+8), w(k0+9)));
    g_bfrag[idx] = make_uint2(*reinterpret_cast<uint32_t*>(&b0),
                              *reinterpret_cast<uint32_t*>(&b1));
}

// ---------------------------------------------------------------------------
// mma.sync helpers (fp16 in, fp32 accum, m16n8k16)
// ---------------------------------------------------------------------------
__device__ __forceinline__ void mma16816(float c[4], const uint32_t a[4],
                                         uint32_t b0, uint32_t b1) {
    asm volatile(
        "mma.sync.aligned.m16n8k16.row.col.f32.f16.f16.f32 "
        "{%0,%1,%2,%3}, {%4,%5,%6,%7}, {%8,%9}, {%0,%1,%2,%3};"
        : "+f"(c[0]), "+f"(c[1]), "+f"(c[2]), "+f"(c[3])
        : "r"(a[0]), "r"(a[1]), "r"(a[2]), "r"(a[3]), "r"(b0), "r"(b1));
}
__device__ __forceinline__ void cvt_hilo(float2 v, uint32_t &h, uint32_t &l) {
    __half2 hb = __float22half2_rn(v);
    float2 hf = __half22float2(hb);
    __half2 lb = __float22half2_rn(make_float2(v.x - hf.x, v.y - hf.y));
    h = *reinterpret_cast<uint32_t*>(&hb);
    l = *reinterpret_cast<uint32_t*>(&lb);
}

// ---------------------------------------------------------------------------
// z projection via mma.sync fp16 2-term: C[262144][24] = z[.][384] @ Wt^T
// ---------------------------------------------------------------------------
__device__ __forceinline__ void load_a(const float* p, float2 A[2][4]) {
    A[0][0] = *(const float2*)(p);
    A[0][1] = *(const float2*)(p + 8*CS);
    A[0][2] = *(const float2*)(p + 8);
    A[0][3] = *(const float2*)(p + 8*CS + 8);
    A[1][0] = *(const float2*)(p + 16*CS);
    A[1][1] = *(const float2*)(p + 24*CS);
    A[1][2] = *(const float2*)(p + 16*CS + 8);
    A[1][3] = *(const float2*)(p + 24*CS + 8);
}

__device__ __forceinline__ void do_step(const uint2* __restrict__ bp, int lane,
                                        float2 A[2][4], float acc[2][3][4]) {
    uint2 bf[3];
    #pragma unroll
    for (int nc = 0; nc < 3; nc++) bf[nc] = bp[nc*32 + lane];
    #pragma unroll
    for (int mt = 0; mt < 2; mt++) {
        uint32_t ah[4], al[4];
        #pragma unroll
        for (int i = 0; i < 4; i++) cvt_hilo(A[mt][i], ah[i], al[i]);
        #pragma unroll
        for (int nc = 0; nc < 3; nc++) {
            mma16816(acc[mt][nc], ah, bf[nc].x, bf[nc].y);
            mma16816(acc[mt][nc], al, bf[nc].x, bf[nc].y);
        }
    }
}

__global__ void __launch_bounds__(256, 2) zproj_mma_kernel(
    const float* __restrict__ z,
    const float* __restrict__ bb, const float* __restrict__ bg,
    float* __restrict__ bias_g)
{
    const int tid  = threadIdx.x;
    const int wid  = tid >> 5, lane = tid & 31;
    const int gid  = lane >> 2, qid = lane & 3;
    const size_t warpbase = (size_t)blockIdx.x * 256 + wid * 32;

    const float* ap = z + (warpbase + gid)*(size_t)CS + qid*2;

    float acc[2][3][4];
    #pragma unroll
    for (int mt = 0; mt < 2; mt++)
        #pragma unroll
        for (int nc = 0; nc < 3; nc++)
            #pragma unroll
            for (int i = 0; i < 4; i++) acc[mt][nc][i] = 0.f;

    float2 A0[2][4], A1[2][4];
    load_a(ap, A0);

    #pragma unroll 1
    for (int kp = 0; kp < 12; kp++) {
        load_a(ap + (kp*2+1)*16, A1);
        do_step(g_bfrag + (kp*2)*96, lane, A0, acc);
        if (kp < 11) load_a(ap + (kp*2+2)*16, A0);
        do_step(g_bfrag + (kp*2+1)*96, lane, A1, acc);
    }

    #pragma unroll
    for (int nc = 0; nc < 3; nc++) {
        int n0 = nc*8 + qid*2;
        float b0v = (n0   < NH) ? bb[n0]   : bg[n0 - NH];
        float b1v = (n0+1 < NH) ? bb[n0+1] : bg[n0+1 - NH];
        #pragma unroll
        for (int mt = 0; mt < 2; mt++) {
            size_t r0 = warpbase + mt*16 + gid;
            bias_g[(size_t)n0    *PLANE + r0    ] = acc[mt][nc][0] + b0v;
            bias_g[(size_t)(n0+1)*PLANE + r0    ] = acc[mt][nc][1] + b1v;
            bias_g[(size_t)n0    *PLANE + r0 + 8] = acc[mt][nc][2] + b0v;
            bias_g[(size_t)(n0+1)*PLANE + r0 + 8] = acc[mt][nc][3] + b1v;
        }
    }
}

// ---------------------------------------------------------------------------
// Tiled GEMM core with register double-buffered prefetch.
// ---------------------------------------------------------------------------
__device__ __forceinline__ void gemm_tile(
    const float* __restrict__ A, const float* __restrict__ B,
    const float* __restrict__ bias, float* __restrict__ C,
    int N, int K, int rb, int cb)
{
    __shared__ __align__(16) float As[16][68];
    __shared__ __align__(16) float Bs[16][64];

    const int tid = threadIdx.x;
    const int tx = tid & 15, ty = tid >> 4;
    const int ar = tid >> 2, aq = tid & 3;
    const int bk = tid >> 4, bn4 = tid & 15;

    float acc[4][4] = {};

    float4 pa = *(const float4*)(A + (size_t)(rb + ar)*K + aq*4);
    float4 pb = *(const float4*)(B + (size_t)bk*N + cb + bn4*4);

    for (int kc = 0; kc < K; kc += 16) {
        __syncthreads();
        As[aq*4+0][ar] = pa.x;
        As[aq*4+1][ar] = pa.y;
        As[aq*4+2][ar] = pa.z;
        As[aq*4+3][ar] = pa.w;
        *(float4*)&Bs[bk][bn4*4] = pb;
        __syncthreads();

        if (kc + 16 < K) {
            pa = *(const float4*)(A + (size_t)(rb + ar)*K + (kc+16) + aq*4);
            pb = *(const float4*)(B + (size_t)(kc+16+bk)*N + cb + bn4*4);
        }

        #pragma unroll
        for (int kk = 0; kk < 16; kk++) {
            float4 a4 = *(const float4*)&As[kk][ty*4];
            float4 b4 = *(const float4*)&Bs[kk][tx*4];
            float aa[4] = {a4.x, a4.y, a4.z, a4.w};
            float bbv[4] = {b4.x, b4.y, b4.z, b4.w};
            #pragma unroll
            for (int i = 0; i < 4; i++)
                #pragma unroll
                for (int j = 0; j < 4; j++)
                    acc[i][j] += aa[i] * bbv[j];
        }
    }

    float4 bias4 = *(const float4*)(bias + cb + tx*4);
    #pragma unroll
    for (int i = 0; i < 4; i++) {
        float4 o = make_float4(acc[i][0] + bias4.x, acc[i][1] + bias4.y,
                               acc[i][2] + bias4.z, acc[i][3] + bias4.w);
        *(float4*)(C + (size_t)(rb + ty*4 + i)*N + cb + tx*4) = o;
    }
}

__global__ void __launch_bounds__(256) sproj_kernel(
    const float* __restrict__ s,
    const float* __restrict__ Wq,  const float* __restrict__ bq,
    const float* __restrict__ Wkv, const float* __restrict__ bkv,
    float* __restrict__ gq, float* __restrict__ gkv)
{
    const int bn = blockIdx.x % 18, bm = blockIdx.x / 18;
    if (bn < 6) gemm_tile(s, Wq,  bq,  gq,  CS,   CS, bm*64, bn*64);
    else        gemm_tile(s, Wkv, bkv, gkv, 2*CS, CS, bm*64, (bn-6)*64);
}

__global__ void __launch_bounds__(256) gemm_bias_kernel(
    const float* __restrict__ A, const float* __restrict__ B,
    const float* __restrict__ bias, float* __restrict__ C,
    int M, int N, int K)
{
    const int nt = N >> 6;
    gemm_tile(A, B, bias, C, N, K, (blockIdx.x / nt)*64, (blockIdx.x % nt)*64);
}

// ---------------------------------------------------------------------------
// Fused attention, 4 query rows per block.
// q hoisted to registers; normalization folded into final output write.
// ---------------------------------------------------------------------------
__global__ void __launch_bounds__(256) attn_kernel(
    const float* __restrict__ qb, const float* __restrict__ kvb,
    const float* __restrict__ bias_g, const int* __restrict__ mask,
    float* __restrict__ ob)
{
    const int h  = blockIdx.x >> 7;
    const int l0 = (blockIdx.x & 127) * 4;
    const int tid = threadIdx.x;

    __shared__ __align__(16) float qsh[4][HD+4];
    __shared__ __align__(16) float ksh[64][HD+4];
    __shared__ __align__(16) float psh[LSEQ][4];
    __shared__ int   msh[LSEQ];
    __shared__ int   mrow[4];
    __shared__ float redm[8][4], reds[8][4];
    __shared__ float invsh[4];
    __shared__ float vred[8][4][HD+1];

    if (tid < 128) qsh[tid>>5][tid&31] = qb[(size_t)(l0 + (tid>>5))*CS + h*HD + (tid&31)];
    if (tid < 4)   mrow[tid] = mask[l0 + tid];
    msh[tid]       = mask[tid];
    msh[tid + 256] = mask[tid + 256];
    __syncthreads();

    const float scale = 0.17677669529663687f;   // 1/sqrt(32)
    const int mlm = tid >> 2;       // 0..63 : m within tile
    const int lq  = tid & 3;        // 0..3  : query row
    const int rowok = mrow[lq];

    // q for this thread's row: loop-invariant -> registers (kills 8 LDS.128/mt)
    float4 qr[8];
    #pragma unroll
    for (int i = 0; i < 8; i++) qr[i] = *(const float4*)&qsh[lq][i*4];

    float lo[8], gt[8];
    float lmax = -3.0e38f;

    #pragma unroll
    for (int mt = 0; mt < 8; mt++) {
        __syncthreads();
        #pragma unroll
        for (int i = 0; i < 2; i++) {
            int f = i*256 + tid;
            int r = f >> 3, c4 = f & 7;
            *(float4*)&ksh[r][c4*4] =
                *(const float4*)(kvb + (size_t)(mt*64 + r)*(2*CS) + h*HD + c4*4);
        }
        __syncthreads();

        int m = mt*64 + mlm;
        float dot = 0.f;
        #pragma unroll
        for (int i = 0; i < 8; i++) {
            float4 kv4 = *(const float4*)&ksh[mlm][i*4];
            dot += qr[i].x*kv4.x + qr[i].y*kv4.y + qr[i].z*kv4.z + qr[i].w*kv4.w;
        }
        float bias = bias_g[(size_t)h*PLANE       + (size_t)(l0+lq)*LSEQ + m];
        float gz   = bias_g[(size_t)(NH+h)*PLANE  + (size_t)(l0+lq)*LSEQ + m];
        gt[mt] = 1.f / (1.f + __expf(-gz));
        float lg = dot*scale + bias;
        if (rowok == 0 || msh[m] == 0) lg = -1.0e9f;
        lo[mt] = lg;
        lmax = fmaxf(lmax, lg);
    }

    // reduce among lanes sharing lq (stride-4 groups), then across warps
    #pragma unroll
    for (int o = 4; o < 32; o <<= 1) lmax = fmaxf(lmax, __shfl_xor_sync(0xffffffffu, lmax, o));
    if ((tid & 31) < 4) redm[tid>>5][tid&3] = lmax;
    __syncthreads();
    float rm = redm[0][lq];
    #pragma unroll
    for (int w = 1; w < 8; w++) rm = fmaxf(rm, redm[w][lq]);

    // exp; store p*gate unnormalized; normalization folded into final write
    float lsum = 0.f;
    #pragma unroll
    for (int mt = 0; mt < 8; mt++) {
        float p = __expf(lo[mt] - rm);
        lsum += p;
        psh[mt*64 + mlm][lq] = p * gt[mt];
    }
    #pragma unroll
    for (int o = 4; o < 32; o <<= 1) lsum += __shfl_xor_sync(0xffffffffu, lsum, o);
    if ((tid & 31) < 4) reds[tid>>5][tid&3] = lsum;
    __syncthreads();
    if (tid < 4) {
        float rs = 0.f;
        #pragma unroll
        for (int w = 0; w < 8; w++) rs += reds[w][tid];
        invsh[tid] = 1.f / rs;
    }
    __syncthreads();

    // o[l][d] = inv_l * sum_m psh[m][l] * v[m][d]
    const int d = tid & 31, g = tid >> 5;
    float oa0 = 0.f, oa1 = 0.f, oa2 = 0.f, oa3 = 0.f;
    const float* vbase = kvb + CS + h*HD + d;
    #pragma unroll 4
    for (int m = g; m < LSEQ; m += 8) {
        float vv = vbase[(size_t)m*(2*CS)];
        float4 pp = *(const float4*)&psh[m][0];
        oa0 += pp.x*vv; oa1 += pp.y*vv; oa2 += pp.z*vv; oa3 += pp.w*vv;
    }
    vred[g][0][d] = oa0;
    vred[g][1][d] = oa1;
    vred[g][2][d] = oa2;
    vred[g][3][d] = oa3;
    __syncthreads();
    if (tid < 128) {
        int l = tid >> 5, dd = tid & 31;
        float s = 0.f;
        #pragma unroll
        for (int gg = 0; gg < 8; gg++) s += vred[gg][l][dd];
        ob[(size_t)(l0+l)*CS + h*HD + dd] = s * invsh[l];
    }
}

// ---------------------------------------------------------------------------
// Launch
// ---------------------------------------------------------------------------
extern "C" void kernel_launch(void* const* d_in, const int* in_sizes, int n_in,
                              void* d_out, int out_size)
{
    (void)in_sizes; (void)n_in; (void)out_size;
    const float* s    = (const float*)d_in[0];
    const float* z    = (const float*)d_in[1];
    const int*   mask = (const int*)  d_in[2];
    const float* Wq   = (const float*)d_in[3];
    const float* bq   = (const float*)d_in[4];
    const float* Wkv  = (const float*)d_in[5];
    const float* bkv  = (const float*)d_in[6];
    const float* Wb   = (const float*)d_in[7];
    const float* bb   = (const float*)d_in[8];
    const float* Wg   = (const float*)d_in[9];
    const float* bg   = (const float*)d_in[10];
    const float* Wout = (const float*)d_in[11];
    const float* bout = (const float*)d_in[12];
    float* out = (float*)d_out;

    float *gq, *gkv, *gbg, *go;
    cudaGetSymbolAddress((void**)&gq,  g_q);
    cudaGetSymbolAddress((void**)&gkv, g_kv);
    cudaGetSymbolAddress((void**)&gbg, g_biasg);
    cudaGetSymbolAddress((void**)&go,  g_o);

    bprep_kernel<<<9, 256>>>(Wb, Wg);
    sproj_kernel<<<8*18, 256>>>(s, Wq, bq, Wkv, bkv, gq, gkv);
    zproj_mma_kernel<<<ZROWS/256, 256>>>(z, bb, bg, gbg);
    attn_kernel<<<NH*(LSEQ/4), 256>>>(gq, gkv, gbg, mask, go);
    gemm_bias_kernel<<<(LSEQ/64)*(CS/64), 256>>>(go, Wout, bout, out, LSEQ, CS, CS);
}

// round 14
// speedup vs baseline: 1.1572x; 1.1572x over previous
#include <cuda_runtime.h>
#include <cuda_bf16.h>
#include <cuda_fp16.h>
#include <cstdint>

// ---------------------------------------------------------------------------
// Problem constants: B=1, L=512, C_S=384, H=12, D=32
// ---------------------------------------------------------------------------
#define LSEQ   512
#define CS     384
#define NH     12
#define HD     32
#define ZROWS  (LSEQ*LSEQ)
#define PLANE  (LSEQ*LSEQ)

// Scratch (device globals: no allocation inside kernel_launch)
__device__ float g_q[LSEQ*CS];
__device__ float g_kv[LSEQ*2*CS];
__device__ float g_biasg[24ull*PLANE];   // n<12: bias head n ; n>=12: gate logit head n-12
__device__ float g_o[LSEQ*CS];
// B in mma-fragment order: [ks(24)][nc(3)][lane(32)] -> uint2 {b0(half2), b1(half2)}
__device__ uint2 g_bfrag[24*3*32];

// ---------------------------------------------------------------------------
// W prep: fused weights -> fp16 fragment layout.
// ---------------------------------------------------------------------------
__global__ void bprep_kernel(const float* __restrict__ Wb, const float* __restrict__ Wg) {
    int idx = blockIdx.x*256 + threadIdx.x;
    if (idx >= 24*3*32) return;
    int lane = idx & 31, step = idx >> 5;
    int ks = step / 3, nc = step % 3;
    int gid = lane >> 2, qid = lane & 3;
    int n = nc*8 + gid;
    int k0 = ks*16 + qid*2;

    auto w = [&](int k) -> float {
        return (n < NH) ? Wb[k*NH + n] : Wg[k*NH + (n - NH)];
    };
    __half2 b0 = __float22half2_rn(make_float2(w(k0),   w(k0+1)));
    __half2 b1 = __float22half2_rn(make_float2(w(k0+8), w(k0+9)));
    g_bfrag[idx] = make_uint2(*reinterpret_cast<uint32_t*>(&b0),
                              *reinterpret_cast<uint32_t*>(&b1));
}

// ---------------------------------------------------------------------------
// mma.sync helpers (fp16 in, fp32 accum, m16n8k16)
// ---------------------------------------------------------------------------
__device__ __forceinline__ void mma16816(float c[4], const uint32_t a[4],
                                         uint32_t b0, uint32_t b1) {
    asm volatile(
        "mma.sync.aligned.m16n8k16.row.col.f32.f16.f16.f32 "
        "{%0,%1,%2,%3}, {%4,%5,%6,%7}, {%8,%9}, {%0,%1,%2,%3};"
        : "+f"(c[0]), "+f"(c[1]), "+f"(c[2]), "+f"(c[3])
        : "r"(a[0]), "r"(a[1]), "r"(a[2]), "r"(a[3]), "r"(b0), "r"(b1));
}
__device__ __forceinline__ void cvt_hilo(float2 v, uint32_t &h, uint32_t &l) {
    __half2 hb = __float22half2_rn(v);
    float2 hf = __half22float2(hb);
    __half2 lb = __float22half2_rn(make_float2(v.x - hf.x, v.y - hf.y));
    h = *reinterpret_cast<uint32_t*>(&hb);
    l = *reinterpret_cast<uint32_t*>(&lb);
}

// ---------------------------------------------------------------------------
// z projection via mma.sync fp16 2-term: C[262144][24] = z[.][384] @ Wt^T
// ---------------------------------------------------------------------------
__device__ __forceinline__ void load_a(const float* p, float2 A[2][4]) {
    A[0][0] = *(const float2*)(p);
    A[0][1] = *(const float2*)(p + 8*CS);
    A[0][2] = *(const float2*)(p + 8);
    A[0][3] = *(const float2*)(p + 8*CS + 8);
    A[1][0] = *(const float2*)(p + 16*CS);
    A[1][1] = *(const float2*)(p + 24*CS);
    A[1][2] = *(const float2*)(p + 16*CS + 8);
    A[1][3] = *(const float2*)(p + 24*CS + 8);
}

__device__ __forceinline__ void do_step(const uint2* __restrict__ bp, int lane,
                                        float2 A[2][4], float acc[2][3][4]) {
    uint2 bf[3];
    #pragma unroll
    for (int nc = 0; nc < 3; nc++) bf[nc] = bp[nc*32 + lane];
    #pragma unroll
    for (int mt = 0; mt < 2; mt++) {
        uint32_t ah[4], al[4];
        #pragma unroll
        for (int i = 0; i < 4; i++) cvt_hilo(A[mt][i], ah[i], al[i]);
        #pragma unroll
        for (int nc = 0; nc < 3; nc++) {
            mma16816(acc[mt][nc], ah, bf[nc].x, bf[nc].y);
            mma16816(acc[mt][nc], al, bf[nc].x, bf[nc].y);
        }
    }
}

__global__ void __launch_bounds__(256, 2) zproj_mma_kernel(
    const float* __restrict__ z,
    const float* __restrict__ bb, const float* __restrict__ bg,
    float* __restrict__ bias_g)
{
    const int tid  = threadIdx.x;
    const int wid  = tid >> 5, lane = tid & 31;
    const int gid  = lane >> 2, qid = lane & 3;
    const size_t warpbase = (size_t)blockIdx.x * 256 + wid * 32;

    const float* ap = z + (warpbase + gid)*(size_t)CS + qid*2;

    float acc[2][3][4];
    #pragma unroll
    for (int mt = 0; mt < 2; mt++)
        #pragma unroll
        for (int nc = 0; nc < 3; nc++)
            #pragma unroll
            for (int i = 0; i < 4; i++) acc[mt][nc][i] = 0.f;

    float2 A0[2][4], A1[2][4];
    load_a(ap, A0);

    #pragma unroll 1
    for (int kp = 0; kp < 12; kp++) {
        load_a(ap + (kp*2+1)*16, A1);
        do_step(g_bfrag + (kp*2)*96, lane, A0, acc);
        if (kp < 11) load_a(ap + (kp*2+2)*16, A0);
        do_step(g_bfrag + (kp*2+1)*96, lane, A1, acc);
    }

    #pragma unroll
    for (int nc = 0; nc < 3; nc++) {
        int n0 = nc*8 + qid*2;
        float b0v = (n0   < NH) ? bb[n0]   : bg[n0 - NH];
        float b1v = (n0+1 < NH) ? bb[n0+1] : bg[n0+1 - NH];
        #pragma unroll
        for (int mt = 0; mt < 2; mt++) {
            size_t r0 = warpbase + mt*16 + gid;
            bias_g[(size_t)n0    *PLANE + r0    ] = acc[mt][nc][0] + b0v;
            bias_g[(size_t)(n0+1)*PLANE + r0    ] = acc[mt][nc][1] + b1v;
            bias_g[(size_t)n0    *PLANE + r0 + 8] = acc[mt][nc][2] + b0v;
            bias_g[(size_t)(n0+1)*PLANE + r0 + 8] = acc[mt][nc][3] + b1v;
        }
    }
}

// ---------------------------------------------------------------------------
// Tiled GEMM core with register double-buffered prefetch.
// ---------------------------------------------------------------------------
__device__ __forceinline__ void gemm_tile(
    const float* __restrict__ A, const float* __restrict__ B,
    const float* __restrict__ bias, float* __restrict__ C,
    int N, int K, int rb, int cb)
{
    __shared__ __align__(16) float As[16][68];
    __shared__ __align__(16) float Bs[16][64];

    const int tid = threadIdx.x;
    const int tx = tid & 15, ty = tid >> 4;
    const int ar = tid >> 2, aq = tid & 3;
    const int bk = tid >> 4, bn4 = tid & 15;

    float acc[4][4] = {};

    float4 pa = *(const float4*)(A + (size_t)(rb + ar)*K + aq*4);
    float4 pb = *(const float4*)(B + (size_t)bk*N + cb + bn4*4);

    for (int kc = 0; kc < K; kc += 16) {
        __syncthreads();
        As[aq*4+0][ar] = pa.x;
        As[aq*4+1][ar] = pa.y;
        As[aq*4+2][ar] = pa.z;
        As[aq*4+3][ar] = pa.w;
        *(float4*)&Bs[bk][bn4*4] = pb;
        __syncthreads();

        if (kc + 16 < K) {
            pa = *(const float4*)(A + (size_t)(rb + ar)*K + (kc+16) + aq*4);
            pb = *(const float4*)(B + (size_t)(kc+16+bk)*N + cb + bn4*4);
        }

        #pragma unroll
        for (int kk = 0; kk < 16; kk++) {
            float4 a4 = *(const float4*)&As[kk][ty*4];
            float4 b4 = *(const float4*)&Bs[kk][tx*4];
            float aa[4] = {a4.x, a4.y, a4.z, a4.w};
            float bbv[4] = {b4.x, b4.y, b4.z, b4.w};
            #pragma unroll
            for (int i = 0; i < 4; i++)
                #pragma unroll
                for (int j = 0; j < 4; j++)
                    acc[i][j] += aa[i] * bbv[j];
        }
    }

    float4 bias4 = *(const float4*)(bias + cb + tx*4);
    #pragma unroll
    for (int i = 0; i < 4; i++) {
        float4 o = make_float4(acc[i][0] + bias4.x, acc[i][1] + bias4.y,
                               acc[i][2] + bias4.z, acc[i][3] + bias4.w);
        *(float4*)(C + (size_t)(rb + ty*4 + i)*N + cb + tx*4) = o;
    }
}

__global__ void __launch_bounds__(256) sproj_kernel(
    const float* __restrict__ s,
    const float* __restrict__ Wq,  const float* __restrict__ bq,
    const float* __restrict__ Wkv, const float* __restrict__ bkv,
    float* __restrict__ gq, float* __restrict__ gkv)
{
    const int bn = blockIdx.x % 18, bm = blockIdx.x / 18;
    if (bn < 6) gemm_tile(s, Wq,  bq,  gq,  CS,   CS, bm*64, bn*64);
    else        gemm_tile(s, Wkv, bkv, gkv, 2*CS, CS, bm*64, (bn-6)*64);
}

__global__ void __launch_bounds__(256) gemm_bias_kernel(
    const float* __restrict__ A, const float* __restrict__ B,
    const float* __restrict__ bias, float* __restrict__ C,
    int M, int N, int K)
{
    const int nt = N >> 6;
    gemm_tile(A, B, bias, C, N, K, (blockIdx.x / nt)*64, (blockIdx.x % nt)*64);
}

// ---------------------------------------------------------------------------
// Fused attention (round-8 proven: 46.4us). 4 query rows per block.
// ---------------------------------------------------------------------------
__global__ void __launch_bounds__(256) attn_kernel(
    const float* __restrict__ qb, const float* __restrict__ kvb,
    const float* __restrict__ bias_g, const int* __restrict__ mask,
    float* __restrict__ ob)
{
    const int h  = blockIdx.x >> 7;
    const int l0 = (blockIdx.x & 127) * 4;
    const int tid = threadIdx.x;

    __shared__ __align__(16) float qsh[4][HD+4];
    __shared__ __align__(16) float ksh[64][HD+4];
    __shared__ __align__(16) float psh[LSEQ][4];
    __shared__ int   msh[LSEQ];
    __shared__ int   mrow[4];
    __shared__ float redm[8][4], reds[8][4];
    __shared__ float vred[8][4][HD+1];

    if (tid < 128) qsh[tid>>5][tid&31] = qb[(size_t)(l0 + (tid>>5))*CS + h*HD + (tid&31)];
    if (tid < 4)   mrow[tid] = mask[l0 + tid];
    msh[tid]       = mask[tid];
    msh[tid + 256] = mask[tid + 256];
    __syncthreads();

    const float scale = 0.17677669529663687f;   // 1/sqrt(32)
    const int mlm = tid >> 2;
    const int lq  = tid & 3;
    const int rowok = mrow[lq];

    float lo[8], gt[8];
    float lmax = -3.0e38f;

    #pragma unroll
    for (int mt = 0; mt < 8; mt++) {
        __syncthreads();
        #pragma unroll
        for (int i = 0; i < 2; i++) {
            int f = i*256 + tid;
            int r = f >> 3, c4 = f & 7;
            *(float4*)&ksh[r][c4*4] =
                *(const float4*)(kvb + (size_t)(mt*64 + r)*(2*CS) + h*HD + c4*4);
        }
        __syncthreads();

        int m = mt*64 + mlm;
        float dot = 0.f;
        #pragma unroll
        for (int i = 0; i < 8; i++) {
            float4 kv4 = *(const float4*)&ksh[mlm][i*4];
            float4 q4  = *(const float4*)&qsh[lq][i*4];
            dot += q4.x*kv4.x + q4.y*kv4.y + q4.z*kv4.z + q4.w*kv4.w;
        }
        float bias = bias_g[(size_t)h*PLANE       + (size_t)(l0+lq)*LSEQ + m];
        float gz   = bias_g[(size_t)(NH+h)*PLANE  + (size_t)(l0+lq)*LSEQ + m];
        gt[mt] = 1.f / (1.f + __expf(-gz));
        float lg = dot*scale + bias;
        if (rowok == 0 || msh[m] == 0) lg = -1.0e9f;
        lo[mt] = lg;
        lmax = fmaxf(lmax, lg);
    }

    #pragma unroll
    for (int o = 4; o < 32; o <<= 1) lmax = fmaxf(lmax, __shfl_xor_sync(0xffffffffu, lmax, o));
    if ((tid & 31) < 4) redm[tid>>5][tid&3] = lmax;
    __syncthreads();
    float rm = redm[0][lq];
    #pragma unroll
    for (int w = 1; w < 8; w++) rm = fmaxf(rm, redm[w][lq]);

    float p[8];
    float lsum = 0.f;
    #pragma unroll
    for (int mt = 0; mt < 8; mt++) { p[mt] = __expf(lo[mt] - rm); lsum += p[mt]; }
    #pragma unroll
    for (int o = 4; o < 32; o <<= 1) lsum += __shfl_xor_sync(0xffffffffu, lsum, o);
    if ((tid & 31) < 4) reds[tid>>5][tid&3] = lsum;
    __syncthreads();
    float rs = 0.f;
    #pragma unroll
    for (int w = 0; w < 8; w++) rs += reds[w][lq];
    float inv = 1.f / rs;

    #pragma unroll
    for (int mt = 0; mt < 8; mt++)
        psh[mt*64 + mlm][lq] = p[mt] * inv * gt[mt];
    __syncthreads();

    const int d = tid & 31, g = tid >> 5;
    float oa0 = 0.f, oa1 = 0.f, oa2 = 0.f, oa3 = 0.f;
    const float* vbase = kvb + CS + h*HD + d;
    #pragma unroll 4
    for (int m = g; m < LSEQ; m += 8) {
        float vv = vbase[(size_t)m*(2*CS)];
        float4 pp = *(const float4*)&psh[m][0];
        oa0 += pp.x*vv; oa1 += pp.y*vv; oa2 += pp.z*vv; oa3 += pp.w*vv;
    }
    vred[g][0][d] = oa0;
    vred[g][1][d] = oa1;
    vred[g][2][d] = oa2;
    vred[g][3][d] = oa3;
    __syncthreads();
    if (tid < 128) {
        int l = tid >> 5, dd = tid & 31;
        float s = 0.f;
        #pragma unroll
        for (int gg = 0; gg < 8; gg++) s += vred[gg][l][dd];
        ob[(size_t)(l0+l)*CS + h*HD + dd] = s;
    }
}

// ---------------------------------------------------------------------------
// Launch: sproj runs on a side stream concurrently with zproj (event fork/join).
// Stream/event objects are created once (host-side only, no device memory).
// ---------------------------------------------------------------------------
extern "C" void kernel_launch(void* const* d_in, const int* in_sizes, int n_in,
                              void* d_out, int out_size)
{
    (void)in_sizes; (void)n_in; (void)out_size;
    const float* s    = (const float*)d_in[0];
    const float* z    = (const float*)d_in[1];
    const int*   mask = (const int*)  d_in[2];
    const float* Wq   = (const float*)d_in[3];
    const float* bq   = (const float*)d_in[4];
    const float* Wkv  = (const float*)d_in[5];
    const float* bkv  = (const float*)d_in[6];
    const float* Wb   = (const float*)d_in[7];
    const float* bb   = (const float*)d_in[8];
    const float* Wg   = (const float*)d_in[9];
    const float* bg   = (const float*)d_in[10];
    const float* Wout = (const float*)d_in[11];
    const float* bout = (const float*)d_in[12];
    float* out = (float*)d_out;

    float *gq, *gkv, *gbg, *go;
    cudaGetSymbolAddress((void**)&gq,  g_q);
    cudaGetSymbolAddress((void**)&gkv, g_kv);
    cudaGetSymbolAddress((void**)&gbg, g_biasg);
    cudaGetSymbolAddress((void**)&go,  g_o);

    static cudaStream_t side = nullptr;
    static cudaEvent_t  e_fork = nullptr, e_join = nullptr;
    if (side == nullptr) {
        cudaStreamCreateWithFlags(&side, cudaStreamNonBlocking);
        cudaEventCreateWithFlags(&e_fork, cudaEventDisableTiming);
        cudaEventCreateWithFlags(&e_join, cudaEventDisableTiming);
    }

    // Fork: side stream depends on everything prior on the main stream.
    cudaEventRecord(e_fork, 0);
    cudaStreamWaitEvent(side, e_fork, 0);

    // Side stream: q/kv projection (independent of z path)
    sproj_kernel<<<8*18, 256, 0, side>>>(s, Wq, bq, Wkv, bkv, gq, gkv);
    cudaEventRecord(e_join, side);

    // Main stream: z path (the big DRAM-bound GEMM)
    bprep_kernel<<<9, 256>>>(Wb, Wg);
    zproj_mma_kernel<<<ZROWS/256, 256>>>(z, bb, bg, gbg);

    // Join: attn needs both sproj and zproj results.
    cudaStreamWaitEvent(0, e_join, 0);
    attn_kernel<<<NH*(LSEQ/4), 256>>>(gq, gkv, gbg, mask, go);
    gemm_bias_kernel<<<(LSEQ/64)*(CS/64), 256>>>(go, Wout, bout, out, LSEQ, CS, CS);
}